// round 1
// baseline (speedup 1.0000x reference)
#include <cuda_runtime.h>
#include <cuda_bf16.h>

// HamiltonianLinearFlow: out[t,n,:] = expm( (1+0.01*tanh(x_n^T A x_n)) * t_t * (J@A) ) @ x_n
// A = sym(M + M0), 16x16. Key insight: expm argument = scalar(t,n) * fixed matrix JA,
// and only its action on x_n is needed -> per-n Taylor/Krylov vectors
//   v_k = (c_n JA)^k x_n / k!,   out[t,n] = sum_{k=0..K} t^k v_k.
// K=16 terms; ||tau*JA|| <~ 0.8 so truncation error ~1e-16, far under 1e-3 gate.

#define MDIM 16
#define TPTS 32
#define KTERMS 16

__global__ __launch_bounds__(256, 4)
void ham_flow_kernel(const float* __restrict__ x,
                     const float* __restrict__ tt,
                     const float* __restrict__ Mm,
                     const float* __restrict__ Jm,
                     const float* __restrict__ M0,
                     float* __restrict__ out,
                     int N)
{
    __shared__ float A_sh[MDIM][MDIM + 1];
    __shared__ float JA_sh[MDIM][MDIM + 1];
    __shared__ float t_sh[TPTS];

    const int tid = threadIdx.x;

    // --- Per-block redundant setup (cheap; avoids extra launch) ---
    {
        int i = tid >> 4, j = tid & 15;
        float a = 0.5f * ((Mm[i * 16 + j] + M0[i * 16 + j]) +
                          (Mm[j * 16 + i] + M0[j * 16 + i]));
        A_sh[i][j] = a;
    }
    if (tid < TPTS) t_sh[tid] = tt[tid];
    __syncthreads();
    {
        int i = tid >> 4, j = tid & 15;
        float s = 0.f;
        #pragma unroll
        for (int k = 0; k < MDIM; k++) s += Jm[i * 16 + k] * A_sh[k][j];
        JA_sh[i][j] = s;
    }
    __syncthreads();

    // --- Per-sample work: 16 lanes per sample (half-warp segments) ---
    const int lane = tid & 31;
    const int seg  = lane & 16;          // segment base within warp (0 or 16)
    const int i    = lane & 15;          // component index
    const int n    = blockIdx.x * 16 + (tid >> 4);
    if (n >= N) return;

    const float xv = x[n * MDIM + i];

    // H = x^T A x  (A symmetric)
    float s = 0.f;
    #pragma unroll
    for (int j = 0; j < MDIM; j++)
        s += A_sh[i][j] * __shfl_sync(0xffffffffu, xv, seg | j);
    float hred = xv * s;
    #pragma unroll
    for (int off = 8; off; off >>= 1)
        hred += __shfl_xor_sync(0xffffffffu, hred, off);   // stays within 16-lane segment

    const float c = 1.0f + 0.01f * tanhf(hred);

    // Row i of (c * JA) in registers
    float row[MDIM];
    #pragma unroll
    for (int j = 0; j < MDIM; j++) row[j] = c * JA_sh[i][j];

    // Krylov/Taylor vectors: v_k = (c JA)^k x / k!
    float vk[KTERMS];
    float v = xv;
    #pragma unroll
    for (int k = 1; k <= KTERMS; k++) {
        float nv = 0.f;
        #pragma unroll
        for (int j = 0; j < MDIM; j++)
            nv += row[j] * __shfl_sync(0xffffffffu, v, seg | j);
        v = nv * (1.0f / (float)k);
        vk[k - 1] = v;
    }

    // out[t,n,i] = x_i + sum_k t^k vk[k]
    const size_t plane = (size_t)N * MDIM;
    #pragma unroll
    for (int t = 0; t < TPTS; t++) {
        const float tv = t_sh[t];
        float pw  = tv;
        float acc = xv;
        #pragma unroll
        for (int k = 0; k < KTERMS; k++) {
            acc = fmaf(pw, vk[k], acc);
            pw *= tv;
        }
        out[(size_t)t * plane + (size_t)n * MDIM + i] = acc;
    }
}

extern "C" void kernel_launch(void* const* d_in, const int* in_sizes, int n_in,
                              void* d_out, int out_size) {
    const float* x  = (const float*)d_in[0];   // (N, 16)
    const float* tt = (const float*)d_in[1];   // (32,)
    const float* Mm = (const float*)d_in[2];   // (16,16)
    const float* Jm = (const float*)d_in[3];   // (16,16)
    const float* M0 = (const float*)d_in[4];   // (16,16)
    float* out = (float*)d_out;                // (32, N, 16)

    const int N = in_sizes[0] / MDIM;          // 2048
    const int blocks = (N + 15) / 16;          // 16 samples per 256-thread block
    ham_flow_kernel<<<blocks, 256>>>(x, tt, Mm, Jm, M0, out, N);
}

// round 2
// speedup vs baseline: 1.0430x; 1.0430x over previous
#include <cuda_runtime.h>
#include <cuda_bf16.h>

// HamiltonianLinearFlow: out[t,n,:] = expm( c_n * t_t * (J@A) ) @ x_n,
//   c_n = 1 + 0.01*tanh(x_n^T A x_n),  A = sym(M+M0), 16x16.
// expm(c t JA) x = sum_k (c t)^k * G_k x,  G_k = (JA)^k / k!  (sample-independent!)
// Precompute G_1..G_10 per block (log-depth squaring), then all w_k = G_k x are
// independent dot products -> no serial shuffle chain. Horner over t.

#define MDIM 16
#define TPTS 32
#define KT 10          // Taylor terms; remainder ~0.9^11/11! ~ 8e-9
#define GPAD 20        // row stride in floats (80B): float4-aligned, conflict deg 2

__global__ __launch_bounds__(256, 4)
void ham_flow_kernel(const float* __restrict__ x,
                     const float* __restrict__ tt,
                     const float* __restrict__ Mm,
                     const float* __restrict__ Jm,
                     const float* __restrict__ M0,
                     float* __restrict__ out,
                     int N)
{
    __shared__ float A_sh[MDIM][MDIM + 1];
    __shared__ float G[KT + 1][MDIM][GPAD];   // G[k][i][j], k=1..10
    __shared__ float t_sh[TPTS];

    const int tid = threadIdx.x;
    const int gi = tid >> 4, gj = tid & 15;   // one (i,j) element per thread

    // ---- A = sym(M+M0); t ----
    {
        float a = 0.5f * ((Mm[gi * 16 + gj] + M0[gi * 16 + gj]) +
                          (Mm[gj * 16 + gi] + M0[gj * 16 + gi]));
        A_sh[gi][gj] = a;
    }
    if (tid < TPTS) t_sh[tid] = tt[tid];
    __syncthreads();

    // ---- G1 = J @ A ----
    {
        float s = 0.f;
        #pragma unroll
        for (int l = 0; l < MDIM; l++) s += Jm[gi * 16 + l] * A_sh[l][gj];
        G[1][gi][gj] = s;
    }
    __syncthreads();

    // helper: (G[a] @ G[b])[gi][gj] * scale   (scale = a!b!/(a+b)! = 1/C(a+b,a))
    auto matel = [&](int a, int b, float scale) -> float {
        float s = 0.f;
        #pragma unroll
        for (int l = 0; l < MDIM; l++) s += G[a][gi][l] * G[b][l][gj];
        return s * scale;
    };

    // ---- log-depth powers ----
    { float g2 = matel(1, 1, 0.5f);                 __syncthreads();
      G[2][gi][gj] = g2; }                          __syncthreads();
    { float g3 = matel(2, 1, 1.f / 3.f);
      float g4 = matel(2, 2, 1.f / 6.f);            __syncthreads();
      G[3][gi][gj] = g3; G[4][gi][gj] = g4; }       __syncthreads();
    { float g5 = matel(4, 1, 1.f / 5.f);
      float g6 = matel(4, 2, 1.f / 15.f);
      float g7 = matel(4, 3, 1.f / 35.f);
      float g8 = matel(4, 4, 1.f / 70.f);           __syncthreads();
      G[5][gi][gj] = g5; G[6][gi][gj] = g6;
      G[7][gi][gj] = g7; G[8][gi][gj] = g8; }       __syncthreads();
    { float g9  = matel(8, 1, 1.f / 9.f);
      float g10 = matel(8, 2, 1.f / 45.f);          __syncthreads();
      G[9][gi][gj] = g9; G[10][gi][gj] = g10; }     __syncthreads();

    // ---- per-sample: 16 lanes per sample ----
    const int lane = tid & 31;
    const int i = lane & 15;
    const int n = blockIdx.x * 16 + (tid >> 4);
    if (n >= N) return;

    // full x_n vector in registers (64B, shared by 16 lanes via L1)
    float xs[MDIM];
    {
        const float4* xp = (const float4*)(x + (size_t)n * MDIM);
        float4 q0 = __ldg(xp + 0), q1 = __ldg(xp + 1),
               q2 = __ldg(xp + 2), q3 = __ldg(xp + 3);
        xs[0]=q0.x; xs[1]=q0.y; xs[2]=q0.z; xs[3]=q0.w;
        xs[4]=q1.x; xs[5]=q1.y; xs[6]=q1.z; xs[7]=q1.w;
        xs[8]=q2.x; xs[9]=q2.y; xs[10]=q2.z; xs[11]=q2.w;
        xs[12]=q3.x; xs[13]=q3.y; xs[14]=q3.z; xs[15]=q3.w;
    }
    const float xv = xs[i];

    // H = x^T A x: lane i computes (A x)_i, reduce over 16-lane segment
    float s = 0.f;
    #pragma unroll
    for (int j = 0; j < MDIM; j++) s += A_sh[i][j] * xs[j];
    float hred = xv * s;
    #pragma unroll
    for (int off = 8; off; off >>= 1)
        hred += __shfl_xor_sync(0xffffffffu, hred, off);

    const float c = 1.0f + 0.01f * tanhf(hred);

    // w_k[i] = (G_k x)_i  — all independent; G rows read as float4
    float vk[KT];
    #pragma unroll
    for (int k = 1; k <= KT; k++) {
        const float4* g = (const float4*)&G[k][i][0];
        float4 r0 = g[0], r1 = g[1], r2 = g[2], r3 = g[3];
        float a0 = r0.x*xs[0] + r0.y*xs[1] + r0.z*xs[2] + r0.w*xs[3];
        float a1 = r1.x*xs[4] + r1.y*xs[5] + r1.z*xs[6] + r1.w*xs[7];
        float a2 = r2.x*xs[8] + r2.y*xs[9] + r2.z*xs[10] + r2.w*xs[11];
        float a3 = r3.x*xs[12] + r3.y*xs[13] + r3.z*xs[14] + r3.w*xs[15];
        vk[k - 1] = (a0 + a1) + (a2 + a3);
    }

    // out[t,n,i] = x_i + tau*(w1 + tau*(w2 + ... + tau*w10)),  tau = c * t
    const size_t plane = (size_t)N * MDIM;
    float* op = out + (size_t)n * MDIM + i;
    #pragma unroll
    for (int t = 0; t < TPTS; t++) {
        const float tau = c * t_sh[t];
        float acc = vk[KT - 1];
        #pragma unroll
        for (int k = KT - 2; k >= 0; k--) acc = fmaf(tau, acc, vk[k]);
        op[(size_t)t * plane] = fmaf(tau, acc, xv);
    }
}

extern "C" void kernel_launch(void* const* d_in, const int* in_sizes, int n_in,
                              void* d_out, int out_size) {
    const float* x  = (const float*)d_in[0];   // (N, 16)
    const float* tt = (const float*)d_in[1];   // (32,)
    const float* Mm = (const float*)d_in[2];   // (16,16)
    const float* Jm = (const float*)d_in[3];   // (16,16)
    const float* M0 = (const float*)d_in[4];   // (16,16)
    float* out = (float*)d_out;                // (32, N, 16)

    const int N = in_sizes[0] / MDIM;          // 2048
    const int blocks = (N + 15) / 16;          // 16 samples per 256-thread block
    ham_flow_kernel<<<blocks, 256>>>(x, tt, Mm, Jm, M0, out, N);
}